// round 1
// baseline (speedup 1.0000x reference)
#include <cuda_runtime.h>
#include <math_constants.h>

#define BN 2
#define NP 65536
#define MR 128
#define NS 6
#define KK 2048
#define NBS (BN*NS)

// ---- scratch (__device__ globals: allocation-free) ----
__device__ float4        g_comp[NBS][NP];   // compacted candidates (x,y,z, orig idx bits)
__device__ float         g_dmin[NBS][NP];   // FPS running min sq-dist
__device__ unsigned char g_sec [BN][NP];    // sector code 0..6, 255 = invalid
__device__ int g_cnt[BN][NS];
__device__ int g_total[BN];
__device__ int g_nk [BN][NS];
__device__ int g_off[BN][NS];
__device__ int g_stotal[BN];
__device__ int g_buf[BN][KK];

// ---- zero the per-launch accumulators (graph replays re-run this) ----
__global__ void k_init() {
    int t = blockIdx.x * blockDim.x + threadIdx.x;
    if (t < BN * KK) ((int*)g_buf)[t] = 0;
    if (t < BN) g_total[t] = 0;
}

// ---- classify: per point, argmin dist over 128 ROIs, valid flag, sector ----
__global__ void __launch_bounds__(256) k_classify(const float* __restrict__ points,
                                                  const float* __restrict__ rois) {
    __shared__ float4 sroi[MR];  // cx, cy, cz(adjusted), thr = maxdim + 1.6
    int b = blockIdx.y;
    int tid = threadIdx.x;
    if (tid < MR) {
        const float* r = rois + (b * MR + tid) * 7;
        float cx = r[0], cy = r[1], cz = r[2];
        float dx = r[3], dy = r[4], dz = r[5];
        cz = __fadd_rn(cz, __fmul_rn(dz, 0.5f));
        float hx = __fmul_rn(dx, 0.5f), hy = __fmul_rn(dy, 0.5f), hz = __fmul_rn(dz, 0.5f);
        float md = __fsqrt_rn(__fadd_rn(__fadd_rn(__fmul_rn(hx, hx), __fmul_rn(hy, hy)),
                                        __fmul_rn(hz, hz)));
        sroi[tid] = make_float4(cx, cy, cz, __fadd_rn(md, 1.6f));
    }
    __syncthreads();

    int i = blockIdx.x * blockDim.x + tid;
    const float* p = points + ((size_t)b * NP + i) * 3;
    float px = p[0], py = p[1], pz = p[2];

    float best_s  = CUDART_INF_F;   // min over sqrt distances (matches reference)
    float best_d2 = CUDART_INF_F;   // min squared distance (prune)
    int   best_i  = 0;
    #pragma unroll 4
    for (int m = 0; m < MR; m++) {
        float4 c = sroi[m];
        float ax = __fsub_rn(px, c.x);
        float ay = __fsub_rn(py, c.y);
        float az = __fsub_rn(pz, c.z);
        float d2 = __fadd_rn(__fadd_rn(__fmul_rn(ax, ax), __fmul_rn(ay, ay)),
                             __fmul_rn(az, az));
        if (d2 < best_d2) {
            // sqrt monotone => if d2 >= best_d2 then sqrt(d2) >= best_s (skip is safe)
            float sd = __fsqrt_rn(d2);
            if (sd < best_s) { best_s = sd; best_i = m; }  // strict <: first-index tie-break
            best_d2 = d2;
        }
    }
    bool valid = best_s < sroi[best_i].w;

    // sector: floor((atan2(y,x)+pi)/sector_size), clip [0,6]; exact rn replication
    float ang = __fadd_rn(atan2f(py, px), 3.14159265358979323846f);
    float fs  = floorf(__fdiv_rn(ang, 1.04719755119659774615f));
    fs = fminf(fmaxf(fs, 0.0f), 6.0f);
    int s = (int)fs;

    g_sec[b][i] = valid ? (unsigned char)s : (unsigned char)255;

    unsigned mask = __ballot_sync(0xffffffffu, valid);
    if ((tid & 31) == 0 && mask) atomicAdd(&g_total[b], __popc(mask));
}

// ---- stable stream compaction per (b,s): preserves original index order ----
__global__ void __launch_bounds__(1024) k_compact(const float* __restrict__ points) {
    int bs = blockIdx.x;
    int b = bs / NS, s = bs - b * NS;
    __shared__ int wsum[32];
    __shared__ int sBase;
    int tid = threadIdx.x;
    int lane = tid & 31, wid = tid >> 5;
    if (tid == 0) sBase = 0;
    __syncthreads();
    const unsigned char* sec = g_sec[b];
    const float* pts = points + (size_t)b * NP * 3;
    for (int base = 0; base < NP; base += 1024) {
        int i = base + tid;
        bool f = (sec[i] == (unsigned char)s);
        unsigned m = __ballot_sync(0xffffffffu, f);
        int wpos = __popc(m & ((1u << lane) - 1u));
        if (lane == 0) wsum[wid] = __popc(m);
        __syncthreads();
        if (wid == 0) {
            int v = wsum[lane];
            #pragma unroll
            for (int o = 1; o < 32; o <<= 1) {
                int u = __shfl_up_sync(0xffffffffu, v, o);
                if (lane >= o) v += u;
            }
            wsum[lane] = v;  // inclusive prefix of warp sums
        }
        __syncthreads();
        if (f) {
            int pos = sBase + (wid ? wsum[wid - 1] : 0) + wpos;
            float4 q;
            q.x = pts[3 * i];
            q.y = pts[3 * i + 1];
            q.z = pts[3 * i + 2];
            q.w = __int_as_float(i);
            g_comp[bs][pos] = q;
        }
        __syncthreads();
        if (tid == 0) sBase += wsum[31];
        __syncthreads();
    }
    if (tid == 0) g_cnt[b][s] = sBase;
}

// ---- per-sector budgets n_k = min(cnt, ceil(cnt*K/total)), offsets, s_total ----
__global__ void k_budget() {
    int b = threadIdx.x;
    if (b >= BN) return;
    int total = g_total[b];
    if (total < 1) total = 1;
    int sum = 0;
    for (int s = 0; s < NS; s++) {
        int c = g_cnt[b][s];
        float q = __fdiv_rn(__fmul_rn((float)c, 2048.0f), (float)total); // *2048 exact
        int nk = (int)ceilf(q);
        if (nk > c) nk = c;
        g_off[b][s] = sum;
        g_nk[b][s]  = nk;
        sum += nk;
    }
    g_stotal[b] = (sum < 1) ? 1 : sum;
}

// ---- FPS: one block per (b,s); only n_k picks are needed (reference drops the rest) ----
__global__ void __launch_bounds__(1024, 1) k_fps() {
    int bs = blockIdx.x;
    int b = bs / NS, s = bs - b * NS;
    int cnt = g_cnt[b][s];
    int nk  = g_nk[b][s];
    int off = g_off[b][s];
    if (nk <= 0 || off >= KK) return;        // picks at positions >= K are dropped anyway
    int nEff = nk;
    if (off + nEff > KK) nEff = KK - off;

    const float4* __restrict__ comp = g_comp[bs];
    float* __restrict__ dmin = g_dmin[bs];
    __shared__ float rV[32];
    __shared__ int   rP[32];
    __shared__ int   sWin;
    int tid = threadIdx.x, lane = tid & 31, wid = tid >> 5;

    float4 p0 = comp[0];                      // first valid = lowest original index
    if (tid == 0) g_buf[b][off] = __float_as_int(p0.w);
    float lx = p0.x, ly = p0.y, lz = p0.z;

    for (int j = 1; j < nEff; j++) {
        float bv = -CUDART_INF_F;
        int   bp = 0x7fffffff;
        if (j == 1) {
            for (int i = tid; i < cnt; i += 1024) {
                float4 p = comp[i];
                float ax = __fsub_rn(p.x, lx), ay = __fsub_rn(p.y, ly), az = __fsub_rn(p.z, lz);
                float d2 = __fadd_rn(__fadd_rn(__fmul_rn(ax, ax), __fmul_rn(ay, ay)),
                                     __fmul_rn(az, az));
                dmin[i] = d2;                 // min(1e10, d2) == d2 for this data
                if (d2 > bv) { bv = d2; bp = i; }
            }
        } else {
            for (int i = tid; i < cnt; i += 1024) {
                float4 p = comp[i];
                float ax = __fsub_rn(p.x, lx), ay = __fsub_rn(p.y, ly), az = __fsub_rn(p.z, lz);
                float d2 = __fadd_rn(__fadd_rn(__fmul_rn(ax, ax), __fmul_rn(ay, ay)),
                                     __fmul_rn(az, az));
                float dm = fminf(dmin[i], d2);
                dmin[i] = dm;
                if (dm > bv) { bv = dm; bp = i; }  // strict >: lowest index wins ties
            }
        }
        // block argmax (value desc, index asc on tie)
        #pragma unroll
        for (int o = 16; o; o >>= 1) {
            float v = __shfl_down_sync(0xffffffffu, bv, o);
            int   p = __shfl_down_sync(0xffffffffu, bp, o);
            if (v > bv || (v == bv && p < bp)) { bv = v; bp = p; }
        }
        if (lane == 0) { rV[wid] = bv; rP[wid] = bp; }
        __syncthreads();
        if (wid == 0) {
            bv = rV[lane];
            bp = rP[lane];
            #pragma unroll
            for (int o = 16; o; o >>= 1) {
                float v = __shfl_down_sync(0xffffffffu, bv, o);
                int   p = __shfl_down_sync(0xffffffffu, bp, o);
                if (v > bv || (v == bv && p < bp)) { bv = v; bp = p; }
            }
            if (lane == 0) sWin = bp;
        }
        __syncthreads();
        int w = sWin;
        float4 pw = comp[w];
        lx = pw.x; ly = pw.y; lz = pw.z;
        if (tid == 0) g_buf[b][off + j] = __float_as_int(pw.w);
    }
}

// ---- gather output: out[b][i] = points[b][ buf[b][ i % s_total ] ] ----
__global__ void k_out(const float* __restrict__ points, float* __restrict__ out) {
    int t = blockIdx.x * blockDim.x + threadIdx.x;
    if (t >= BN * KK) return;
    int b = t / KK, i = t - b * KK;
    int st = g_stotal[b];
    int src = g_buf[b][i % st];
    const float* p = points + ((size_t)b * NP + src) * 3;
    out[3 * t + 0] = p[0];
    out[3 * t + 1] = p[1];
    out[3 * t + 2] = p[2];
}

extern "C" void kernel_launch(void* const* d_in, const int* in_sizes, int n_in,
                              void* d_out, int out_size) {
    const float* points = (const float*)d_in[0];  // [2,65536,3] f32
    const float* rois   = (const float*)d_in[1];  // [2,128,7]  f32
    float* out = (float*)d_out;                   // [2,2048,3] f32

    k_init<<<(BN * KK + 255) / 256, 256>>>();
    dim3 gc(NP / 256, BN);
    k_classify<<<gc, 256>>>(points, rois);
    k_compact<<<NBS, 1024>>>(points);
    k_budget<<<1, 32>>>();
    k_fps<<<NBS, 1024>>>();
    k_out<<<(BN * KK + 255) / 256, 256>>>(points, out);
}

// round 2
// speedup vs baseline: 1.3872x; 1.3872x over previous
#include <cuda_runtime.h>
#include <math_constants.h>

#define BN 2
#define NP 65536
#define MR 128
#define NS 6
#define KK 2048
#define NBS (BN*NS)

#define FPS_T 512
#define MAXC 8192
// dyn smem: float4 pts[MAXC] + float dmin[MAXC] + u32 rV[32] + u32 rI[32]
#define SMEM_FPS (MAXC*16 + MAXC*4 + 64*4)

// ---- scratch (__device__ globals: allocation-free) ----
__device__ float4        g_comp[NBS][NP];   // compacted candidates (x,y,z, orig idx bits)
__device__ float         g_dmin[NBS][NP];   // FPS fallback dmin (cnt > MAXC only)
__device__ unsigned char g_sec [BN][NP];    // sector code 0..6, 255 = invalid
__device__ int g_cnt[BN][NS];
__device__ int g_total[BN];
__device__ int g_nk [BN][NS];
__device__ int g_off[BN][NS];
__device__ int g_stotal[BN];
__device__ int g_buf[BN][KK];

// ---- zero per-launch accumulators (graph replays re-run this) ----
__global__ void k_init() {
    int t = blockIdx.x * blockDim.x + threadIdx.x;
    if (t < BN * KK) ((int*)g_buf)[t] = 0;
    if (t < BN) g_total[t] = 0;
}

// ---- classify: branchless d2 argmin + single deferred sqrt; exact cleanup on near-tie ----
__global__ void __launch_bounds__(256) k_classify(const float* __restrict__ points,
                                                  const float* __restrict__ rois) {
    __shared__ float4 sroi[MR];  // cx, cy, cz(adjusted), thr = maxdim + 1.6
    int b = blockIdx.y;
    int tid = threadIdx.x;
    if (tid < MR) {
        const float* r = rois + (b * MR + tid) * 7;
        float cx = r[0], cy = r[1], cz = r[2];
        float dx = r[3], dy = r[4], dz = r[5];
        cz = __fadd_rn(cz, __fmul_rn(dz, 0.5f));
        float hx = __fmul_rn(dx, 0.5f), hy = __fmul_rn(dy, 0.5f), hz = __fmul_rn(dz, 0.5f);
        float md = __fsqrt_rn(__fadd_rn(__fadd_rn(__fmul_rn(hx, hx), __fmul_rn(hy, hy)),
                                        __fmul_rn(hz, hz)));
        sroi[tid] = make_float4(cx, cy, cz, __fadd_rn(md, 1.6f));
    }
    __syncthreads();

    int i = blockIdx.x * blockDim.x + tid;
    const float* p = points + ((size_t)b * NP + i) * 3;
    float px = p[0], py = p[1], pz = p[2];

    // Track min (m1, index bi, strict-<) and runner-up value m2 in d2 space; no branches.
    float m1 = CUDART_INF_F, m2 = CUDART_INF_F;
    int bi = 0;
    #pragma unroll 4
    for (int m = 0; m < MR; m++) {
        float4 c = sroi[m];
        float ax = __fsub_rn(px, c.x);
        float ay = __fsub_rn(py, c.y);
        float az = __fsub_rn(pz, c.z);
        float d2 = __fadd_rn(__fadd_rn(__fmul_rn(ax, ax), __fmul_rn(ay, ay)),
                             __fmul_rn(az, az));
        float mx = fmaxf(d2, m1);       // = old m1 if d2 wins, else d2
        m2 = fminf(m2, mx);             // runner-up value (any index)
        if (d2 < m1) { m1 = d2; bi = m; }  // strict <: first-index tie-break (predicated)
    }
    float s1 = __fsqrt_rn(m1);
    // d2-argmin can differ from the reference's sqrt-argmin only if two d2 values
    // round to the same sqrt. sqrt(m2) > s1 proves no such collision exists.
    if (__fsqrt_rn(m2) == s1) {
        float bsv = CUDART_INF_F; int bi2 = 0;
        for (int m = 0; m < MR; m++) {
            float4 c = sroi[m];
            float ax = __fsub_rn(px, c.x);
            float ay = __fsub_rn(py, c.y);
            float az = __fsub_rn(pz, c.z);
            float d2 = __fadd_rn(__fadd_rn(__fmul_rn(ax, ax), __fmul_rn(ay, ay)),
                                 __fmul_rn(az, az));
            float sd = __fsqrt_rn(d2);
            if (sd < bsv) { bsv = sd; bi2 = m; }
        }
        s1 = bsv; bi = bi2;
    }
    bool valid = s1 < sroi[bi].w;

    // sector: floor((atan2(y,x)+pi)/sector_size), clip [0,6]; exact rn replication
    float ang = __fadd_rn(atan2f(py, px), 3.14159265358979323846f);
    float fs  = floorf(__fdiv_rn(ang, 1.04719755119659774615f));
    fs = fminf(fmaxf(fs, 0.0f), 6.0f);
    int s = (int)fs;

    g_sec[b][i] = valid ? (unsigned char)s : (unsigned char)255;

    unsigned mask = __ballot_sync(0xffffffffu, valid);
    if ((tid & 31) == 0 && mask) atomicAdd(&g_total[b], __popc(mask));
}

// ---- stable stream compaction per (b,s): preserves original index order ----
__global__ void __launch_bounds__(1024) k_compact(const float* __restrict__ points) {
    int bs = blockIdx.x;
    int b = bs / NS, s = bs - b * NS;
    __shared__ int wsum[32];
    __shared__ int sBase;
    int tid = threadIdx.x;
    int lane = tid & 31, wid = tid >> 5;
    if (tid == 0) sBase = 0;
    __syncthreads();
    const unsigned char* sec = g_sec[b];
    const float* pts = points + (size_t)b * NP * 3;
    for (int base = 0; base < NP; base += 1024) {
        int i = base + tid;
        bool f = (sec[i] == (unsigned char)s);
        unsigned m = __ballot_sync(0xffffffffu, f);
        int wpos = __popc(m & ((1u << lane) - 1u));
        if (lane == 0) wsum[wid] = __popc(m);
        __syncthreads();
        if (wid == 0) {
            int v = wsum[lane];
            #pragma unroll
            for (int o = 1; o < 32; o <<= 1) {
                int u = __shfl_up_sync(0xffffffffu, v, o);
                if (lane >= o) v += u;
            }
            wsum[lane] = v;  // inclusive prefix of warp sums
        }
        __syncthreads();
        if (f) {
            int pos = sBase + (wid ? wsum[wid - 1] : 0) + wpos;
            float4 q;
            q.x = pts[3 * i];
            q.y = pts[3 * i + 1];
            q.z = pts[3 * i + 2];
            q.w = __int_as_float(i);
            g_comp[bs][pos] = q;
        }
        __syncthreads();
        if (tid == 0) sBase += wsum[31];
        __syncthreads();
    }
    if (tid == 0) g_cnt[b][s] = sBase;
}

// ---- per-sector budgets n_k = min(cnt, ceil(cnt*K/total)), offsets, s_total ----
__global__ void k_budget() {
    int b = threadIdx.x;
    if (b >= BN) return;
    int total = g_total[b];
    if (total < 1) total = 1;
    int sum = 0;
    for (int s = 0; s < NS; s++) {
        int c = g_cnt[b][s];
        float q = __fdiv_rn(__fmul_rn((float)c, 2048.0f), (float)total);
        int nk = (int)ceilf(q);
        if (nk > c) nk = c;
        g_off[b][s] = sum;
        g_nk[b][s]  = nk;
        sum += nk;
    }
    g_stotal[b] = (sum < 1) ? 1 : sum;
}

// ---- FPS v2: smem-resident candidates + dmin, redux.sync argmax reductions ----
__global__ void __launch_bounds__(FPS_T, 1) k_fps2() {
    int bs = blockIdx.x;
    int b = bs / NS, s = bs - b * NS;
    int cnt = g_cnt[b][s];
    int nk  = g_nk[b][s];
    int off = g_off[b][s];
    if (nk <= 0 || off >= KK) return;   // picks at positions >= K are dropped anyway
    int nEff = nk;
    if (off + nEff > KK) nEff = KK - off;

    extern __shared__ unsigned char sm_raw[];
    float4*   sp = (float4*)sm_raw;            // [MAXC]
    float*    sd = (float*)(sp + MAXC);        // [MAXC]
    unsigned* rV = (unsigned*)(sd + MAXC);     // [32]
    unsigned* rI = rV + 32;                    // [32]
    __shared__ int sWin;

    int tid = threadIdx.x, lane = tid & 31, wid = tid >> 5;
    bool use_sm = (cnt <= MAXC);

    const float4* __restrict__ P;
    float* __restrict__ D;
    if (use_sm) {
        for (int i = tid; i < cnt; i += FPS_T) sp[i] = g_comp[bs][i];
        __syncthreads();
        P = sp; D = sd;
    } else {
        P = g_comp[bs]; D = g_dmin[bs];
    }

    float4 p0 = P[0];                          // first valid = lowest original index
    if (tid == 0) g_buf[b][off] = __float_as_int(p0.w);
    float lx = p0.x, ly = p0.y, lz = p0.z;

    for (int j = 1; j < nEff; j++) {
        float vmax = -1.0f;
        unsigned vidx = 0xffffffffu;
        if (j == 1) {
            for (int i = tid; i < cnt; i += FPS_T) {
                float4 p = P[i];
                float ax = __fsub_rn(p.x, lx), ay = __fsub_rn(p.y, ly), az = __fsub_rn(p.z, lz);
                float d2 = __fadd_rn(__fadd_rn(__fmul_rn(ax, ax), __fmul_rn(ay, ay)),
                                     __fmul_rn(az, az));
                D[i] = d2;                     // min(1e10, d2) == d2 for this data
                if (d2 > vmax) { vmax = d2; vidx = (unsigned)i; }
            }
        } else {
            for (int i = tid; i < cnt; i += FPS_T) {
                float4 p = P[i];
                float ax = __fsub_rn(p.x, lx), ay = __fsub_rn(p.y, ly), az = __fsub_rn(p.z, lz);
                float d2 = __fadd_rn(__fadd_rn(__fmul_rn(ax, ax), __fmul_rn(ay, ay)),
                                     __fmul_rn(az, az));
                float dm = D[i];
                if (d2 < dm) { dm = d2; D[i] = dm; }   // store only on shrink
                if (dm > vmax) { vmax = dm; vidx = (unsigned)i; }  // strict >: lowest idx wins
            }
        }
        // warp argmax via redux: max on float bits (all >= 0), then min index among winners
        unsigned vb = (vmax < 0.0f) ? 0u : __float_as_uint(vmax);
        unsigned wm = __reduce_max_sync(0xffffffffu, vb);
        unsigned ci = (vb == wm) ? vidx : 0xffffffffu;
        unsigned wi = __reduce_min_sync(0xffffffffu, ci);
        if (lane == 0) { rV[wid] = wm; rI[wid] = wi; }
        __syncthreads();
        if (tid < 32) {
            unsigned v2 = (lane < FPS_T / 32) ? rV[lane] : 0u;
            unsigned i2 = (lane < FPS_T / 32) ? rI[lane] : 0xffffffffu;
            unsigned m2 = __reduce_max_sync(0xffffffffu, v2);
            unsigned c2 = (v2 == m2) ? i2 : 0xffffffffu;
            unsigned w2 = __reduce_min_sync(0xffffffffu, c2);
            if (lane == 0) sWin = (w2 == 0xffffffffu) ? 0 : (int)w2;
        }
        __syncthreads();
        int w = sWin;
        float4 pw = P[w];
        lx = pw.x; ly = pw.y; lz = pw.z;
        if (tid == 0) g_buf[b][off + j] = __float_as_int(pw.w);
    }
}

// ---- gather output: out[b][i] = points[b][ buf[b][ i % s_total ] ] ----
__global__ void k_out(const float* __restrict__ points, float* __restrict__ out) {
    int t = blockIdx.x * blockDim.x + threadIdx.x;
    if (t >= BN * KK) return;
    int b = t / KK, i = t - b * KK;
    int st = g_stotal[b];
    int src = g_buf[b][i % st];
    const float* p = points + ((size_t)b * NP + src) * 3;
    out[3 * t + 0] = p[0];
    out[3 * t + 1] = p[1];
    out[3 * t + 2] = p[2];
}

extern "C" void kernel_launch(void* const* d_in, const int* in_sizes, int n_in,
                              void* d_out, int out_size) {
    const float* points = (const float*)d_in[0];  // [2,65536,3] f32
    const float* rois   = (const float*)d_in[1];  // [2,128,7]  f32
    float* out = (float*)d_out;                   // [2,2048,3] f32

    cudaFuncSetAttribute(k_fps2, cudaFuncAttributeMaxDynamicSharedMemorySize, SMEM_FPS);

    k_init<<<(BN * KK + 255) / 256, 256>>>();
    dim3 gc(NP / 256, BN);
    k_classify<<<gc, 256>>>(points, rois);
    k_compact<<<NBS, 1024>>>(points);
    k_budget<<<1, 32>>>();
    k_fps2<<<NBS, FPS_T, SMEM_FPS>>>();
    k_out<<<(BN * KK + 255) / 256, 256>>>(points, out);
}